// round 1
// baseline (speedup 1.0000x reference)
#include <cuda_runtime.h>
#include <math.h>
#include <stdint.h>

// Fixed problem shape: x = float32[32,3,512,512], sign = scalar int, out = float32[1]
#define N_IMG      32
#define PLANE      (512 * 512)        // 262144 pixels per channel
#define BINS       256
#define HB_THREADS 128                // threads per histogram block
#define BIMG       32                 // blocks per image
#define PPB        (PLANE / BIMG)     // 8192 pixels per block
#define F4_PER_BLK (PPB / 4)          // 2048 float4 per channel per block
#define ITERS      (F4_PER_BLK / HB_THREADS)  // 16 iterations per thread

// Global per-image histograms (counts only — S cancels out of H, see analysis).
__device__ unsigned g_cnt[N_IMG * BINS];

// ---------------------------------------------------------------------------
// Kernel 1: zero the global histograms (must run every launch; graph-safe)
// ---------------------------------------------------------------------------
__global__ void ie_zero_kernel() {
    g_cnt[blockIdx.x * 1024 + threadIdx.x] = 0u;
}

// ---------------------------------------------------------------------------
// Kernel 2: per-image histogram.
// Per-thread private u8 histograms in shared memory, conflict-free layout:
//   byte addr = (bin>>2)*512 + tid*4 + (bin&3)
//   -> 32-bit word index = (bin>>2)*128 + tid  -> bank = tid % 32 (always)
// No atomics in the hot loop; each (word) is owned by exactly one thread.
// ---------------------------------------------------------------------------
__device__ __forceinline__ void ie_bump(float a, float b, float c,
                                        unsigned char* h, int tid) {
    // Faithful binning: idx = round_half_even(Y / interval), strict half-open
    // membership (Y > v-eps && Y < v+eps), idx in [0,255].
    const float INTERVAL = 1.0f / 255.0f;        // fl(1/255)
    const float EPS      = 0.5f * (1.0f / 255.0f); // == fl(1/510)

    float y = 0.257f * a + 0.564f * b + 0.098f * c + 0.0625f;
    float f = __fdiv_rn(y, INTERVAL);            // IEEE division like the ref
    int   idx = __float2int_rn(f);               // round-to-nearest-even
    float v = __fmul_rn((float)idx, INTERVAL);
    bool ok = (idx >= 0) && (idx <= 255) && (y > v - EPS) && (y < v + EPS);
    if (ok) {
        int addr = ((idx >> 2) * (HB_THREADS * 4)) + (tid << 2) + (idx & 3);
        h[addr] = (unsigned char)(h[addr] + 1);  // private: no race; <=64 so no overflow
    }
}

__global__ void __launch_bounds__(HB_THREADS, 6)
ie_hist_kernel(const float* __restrict__ x) {
    __shared__ unsigned char h[64 * HB_THREADS * 4];   // 32 KB
    unsigned* h32 = reinterpret_cast<unsigned*>(h);

    const int tid = threadIdx.x;
    const int bi  = blockIdx.x;   // chunk within image, 0..BIMG-1
    const int img = blockIdx.y;   // image, 0..31

    // zero private histograms
    #pragma unroll
    for (int i = tid; i < 64 * HB_THREADS; i += HB_THREADS) h32[i] = 0u;
    __syncthreads();

    const float* base = x + (size_t)img * 3 * PLANE;
    const int chunk = bi * PPB;
    const float4* r4 = reinterpret_cast<const float4*>(base + chunk);
    const float4* g4 = reinterpret_cast<const float4*>(base + PLANE + chunk);
    const float4* b4 = reinterpret_cast<const float4*>(base + 2 * PLANE + chunk);

    #pragma unroll 2
    for (int k = 0; k < ITERS; k++) {
        int i = k * HB_THREADS + tid;            // coalesced: lane-contiguous float4
        float4 r = __ldg(r4 + i);
        float4 g = __ldg(g4 + i);
        float4 b = __ldg(b4 + i);
        ie_bump(r.x, g.x, b.x, h, tid);
        ie_bump(r.y, g.y, b.y, h, tid);
        ie_bump(r.z, g.z, b.z, h, tid);
        ie_bump(r.w, g.w, b.w, h, tid);
    }
    __syncthreads();

    // Flush: thread g (0..63) reduces bin-group g (bins 4g..4g+3) across all
    // 128 copies. Rotated start (g+k)&127 keeps banks distinct per lane.
    if (tid < 64) {
        const int g = tid;
        const unsigned* row = h32 + g * HB_THREADS;
        unsigned a0 = 0, a1 = 0, a2 = 0, a3 = 0;
        #pragma unroll 8
        for (int k = 0; k < HB_THREADS; k++) {
            unsigned w = row[(g + k) & (HB_THREADS - 1)];
            a0 += w & 0xFFu;
            a1 += (w >> 8) & 0xFFu;
            a2 += (w >> 16) & 0xFFu;
            a3 += w >> 24;
        }
        unsigned* dst = g_cnt + img * BINS + g * 4;
        atomicAdd(dst + 0, a0);
        atomicAdd(dst + 1, a1);
        atomicAdd(dst + 2, a2);
        atomicAdd(dst + 3, a3);
    }
}

// ---------------------------------------------------------------------------
// Kernel 3: entropy per image + mean + sign. One block, warp w handles image w.
// H == cnt/N exactly (N = 2^18), matching the ref's S/(pixel*N) to <=3 ulp.
// ---------------------------------------------------------------------------
__global__ void ie_entropy_kernel(const void* __restrict__ signp,
                                  float* __restrict__ out) {
    __shared__ float ent[32];
    const int w = threadIdx.x >> 5;
    const int l = threadIdx.x & 31;
    const float invN = 1.0f / (float)PLANE;

    float s = 0.0f;
    #pragma unroll
    for (int b = l; b < BINS; b += 32) {
        unsigned c = g_cnt[w * BINS + b];
        if (c) {
            float H = (float)c * invN;
            s -= H * log2f(H);
        }
    }
    #pragma unroll
    for (int o = 16; o; o >>= 1) s += __shfl_xor_sync(0xFFFFFFFFu, s, o);
    if (l == 0) ent[w] = s;
    __syncthreads();

    if (threadIdx.x < 32) {
        float e = ent[threadIdx.x];
        #pragma unroll
        for (int o = 16; o; o >>= 1) e += __shfl_xor_sync(0xFFFFFFFFu, e, o);
        if (threadIdx.x == 0) {
            // sign is an integer scalar (int32 or int64 low word on LE);
            // fall back to float bits if it doesn't look like a small int.
            int iv = *(const int*)signp;
            float sv = (iv == 1 || iv == 0 || iv == -1) ? (float)iv
                                                        : __int_as_float(iv);
            out[0] = sv * e * (1.0f / 32.0f);
        }
    }
}

// ---------------------------------------------------------------------------
extern "C" void kernel_launch(void* const* d_in, const int* in_sizes, int n_in,
                              void* d_out, int out_size) {
    (void)in_sizes; (void)n_in; (void)out_size;
    const float* x = (const float*)d_in[0];

    ie_zero_kernel<<<(N_IMG * BINS) / 1024, 1024>>>();
    dim3 grid(BIMG, N_IMG);
    ie_hist_kernel<<<grid, HB_THREADS>>>(x);
    ie_entropy_kernel<<<1, 1024>>>(d_in[1], (float*)d_out);
}